// round 9
// baseline (speedup 1.0000x reference)
#include <cuda_runtime.h>
#include <cstdint>

#define B_   16
#define CIN  256
#define CR   32
#define HW   4096          // 64*64
#define COUT 560           // 32 + 528

// 8 MB scratch: relu(BN(1x1conv(x)))
__device__ float g_z[B_ * CR * HW];

__device__ __forceinline__ unsigned long long pack2(float lo, float hi) {
    unsigned long long r;
    asm("mov.b64 %0, {%1, %2};" : "=l"(r) : "r"(__float_as_uint(lo)), "r"(__float_as_uint(hi)));
    return r;
}
__device__ __forceinline__ unsigned long long fma2(unsigned long long a,
                                                   unsigned long long b,
                                                   unsigned long long c) {
    unsigned long long d;
    asm("fma.rn.f32x2 %0, %1, %2, %3;" : "=l"(d) : "l"(a), "l"(b), "l"(c));
    return d;
}
__device__ __forceinline__ void unpack2(unsigned long long v, float& lo, float& hi) {
    unsigned int l, h;
    asm("mov.b64 {%0, %1}, %2;" : "=r"(l), "=r"(h) : "l"(v));
    lo = __uint_as_float(l);
    hi = __uint_as_float(h);
}

// ---------------------------------------------------------------------------
// Kernel 1: full 1x1 reduce conv + bias + ReLU, minimum DRAM traffic
// (x read once, z written once = 75 MB), K-split resolved INSIDE the block.
// 512 blocks x 512 thr.  Block = 128 pixels.
// Thread = 1 px, 16 out-ch, 128 in-ch  (tid bits: kh | h | p).
//   kh=1 threads deposit partials into smem; kh=0 threads combine + write z.
// 8 ull accs = 16 regs -> no spill without launch_bounds games.
// ---------------------------------------------------------------------------
__global__ __launch_bounds__(512) void k_reduce(
    const float* __restrict__ x, const float* __restrict__ w,
    const float* __restrict__ gamma, const float* __restrict__ beta,
    const float* __restrict__ mean,  const float* __restrict__ var)
{
    __shared__ __align__(16) float wsm[CIN * CR];   // [c][o], BN inv folded (32KB)
    __shared__ float exch[CR * 128];                // partial exchange (16KB)
    __shared__ float inv_s[CR];
    __shared__ float bias_s[CR];

    const int tid = threadIdx.x;
    if (tid < CR) {
        float inv = gamma[tid] * rsqrtf(var[tid] + 1e-5f);
        inv_s[tid]  = inv;
        bias_s[tid] = beta[tid] - mean[tid] * inv;
    }
    __syncthreads();
    for (int i = tid; i < CIN * CR; i += 512) {
        int c = i >> 5, o = i & 31;
        wsm[i] = w[o * CIN + c] * inv_s[o];
    }
    __syncthreads();

    const int kh = tid >> 8;               // K-half        (warp-uniform)
    const int h  = (tid >> 7) & 1;         // out-ch half   (warp-uniform)
    const int p  = tid & 127;              // pixel in block
    const int b  = blockIdx.x >> 5;        // 32 blocks (128 px) per image
    const int s0 = ((blockIdx.x & 31) << 7) + p;

    const float* xp = x + (((size_t)(b * CIN + kh * 128)) << 12) + s0;

    unsigned long long acc[8];             // 16 out channels
#pragma unroll
    for (int m = 0; m < 8; m++) acc[m] = 0ull;

#pragma unroll 4
    for (int c = 0; c < 128; c++) {
        float a = __ldg(xp + ((size_t)c << 12));
        unsigned long long a2 = pack2(a, a);
        const ulonglong2* wr =
            reinterpret_cast<const ulonglong2*>(wsm + (kh * 128 + c) * CR + h * 16);
#pragma unroll
        for (int q = 0; q < 4; q++) {
            ulonglong2 w2 = wr[q];          // 4 out channels (2 f32x2)
            acc[2 * q]     = fma2(a2, w2.x, acc[2 * q]);
            acc[2 * q + 1] = fma2(a2, w2.y, acc[2 * q + 1]);
        }
    }

    // K-half 1 deposits partials
    if (kh == 1) {
#pragma unroll
        for (int m = 0; m < 8; m++) {
            float v0, v1;
            unpack2(acc[m], v0, v1);
            const int ch = h * 16 + 2 * m;
            exch[ch * 128 + p]       = v0;
            exch[(ch + 1) * 128 + p] = v1;
        }
    }
    __syncthreads();

    // K-half 0 combines + bias + ReLU + single z write
    if (kh == 0) {
        float* zp = g_z + (((size_t)(b * CR)) << 12) + s0;
#pragma unroll
        for (int m = 0; m < 8; m++) {
            float v0, v1;
            unpack2(acc[m], v0, v1);
            const int ch = h * 16 + 2 * m;
            zp[(size_t)ch << 12] =
                fmaxf(v0 + exch[ch * 128 + p] + bias_s[ch], 0.f);
            zp[(size_t)(ch + 1) << 12] =
                fmaxf(v1 + exch[(ch + 1) * 128 + p] + bias_s[ch + 1], 0.f);
        }
    }
}

// ---------------------------------------------------------------------------
// Kernel 2: depthwise 3x3 + scale, dual L2-normalize, triu pairs, concat.
// 32x4 pixel tile, 256 threads.  (unchanged from best: 29.7us)
// ---------------------------------------------------------------------------
#define TW 32
#define TH 4
#define ROWW 34                       // TW + 2 halo
#define NPX  204                      // 6 * 34 halo'd pixels per channel
#define CH_STRIDE NPX

__global__ __launch_bounds__(256, 4) void k_head(
    const float* __restrict__ dw, const float* __restrict__ scale,
    float* __restrict__ out)
{
    __shared__ float zt[CR * CH_STRIDE];     // relu'd z tile with halo (25.5KB)
    __shared__ __align__(16) float zc_s[CR * 128];  // conv*scale per pixel (16KB)
    __shared__ float ssz_s[2][128];
    __shared__ float sst_s[2][128];
    __shared__ __align__(16) float invz_s[128];
    __shared__ __align__(16) float invt_s[128];
    __shared__ float dws[CR * 9];
    __shared__ float sc_s[CR];

    const int tid  = threadIdx.x;
    const int lane = tid & 31;
    const int wid  = tid >> 5;
    const int b    = blockIdx.z;
    const int ty0  = blockIdx.y * TH;
    const int tx0  = blockIdx.x * TW;
    const int half = tid >> 7;               // 0 or 1
    const int p    = tid & 127;              // pixel within tile
    const int pty  = p >> 5;
    const int ptx  = p & 31;

    if (tid < CR) sc_s[tid] = scale[tid];
    for (int i = tid; i < CR * 9; i += 256) dws[i] = dw[i];

    // ---- tile load: warp `wid` handles channels wid, wid+8, wid+16, wid+24 ----
    int  offs[7];
    bool vld[7];
#pragma unroll
    for (int it = 0; it < 7; it++) {
        int px = it * 32 + lane;             // 0..223, valid < NPX
        int y  = px / ROWW;
        int xx = px - y * ROWW;
        int gy = ty0 - 1 + y;
        int gx = tx0 - 1 + xx;
        vld[it]  = (px < NPX) && ((unsigned)gy < 64u) && ((unsigned)gx < 64u);
        offs[it] = (gy << 6) + gx;
    }
    const float* zb = g_z + (((size_t)b * CR) << 12);
#pragma unroll
    for (int cc = 0; cc < 4; cc++) {
        const int c = cc * 8 + wid;
        const float* zc0 = zb + ((size_t)c << 12);
        float* st = zt + c * CH_STRIDE;
#pragma unroll
        for (int it = 0; it < 7; it++) {
            float v = vld[it] ? __ldg(zc0 + offs[it]) : 0.f;
            int px = it * 32 + lane;
            if (px < NPX) st[px] = v;
        }
    }
    __syncthreads();

    // ---- conv: each thread does 16 channels for its pixel ----
    {
        float ssz = 0.f, sst = 0.f;
        const int cBase = half * 16;
#pragma unroll
        for (int cc = 0; cc < 16; cc++) {
            const int c = cBase + cc;
            const float* pp = zt + c * CH_STRIDE + pty * ROWW + ptx;
            const float* k9 = dws + c * 9;
            float acc;
            acc = pp[0] * k9[0];
            acc = fmaf(pp[1],            k9[1], acc);
            acc = fmaf(pp[2],            k9[2], acc);
            acc = fmaf(pp[ROWW],         k9[3], acc);
            float ctr = pp[ROWW + 1];
            acc = fmaf(ctr,              k9[4], acc);
            acc = fmaf(pp[ROWW + 2],     k9[5], acc);
            acc = fmaf(pp[2 * ROWW],     k9[6], acc);
            acc = fmaf(pp[2 * ROWW + 1], k9[7], acc);
            acc = fmaf(pp[2 * ROWW + 2], k9[8], acc);
            acc *= sc_s[c];
            zc_s[c * 128 + p] = acc;
            ssz = fmaf(ctr, ctr, ssz);
            sst = fmaf(acc, acc, sst);
        }
        ssz_s[half][p] = ssz;
        sst_s[half][p] = sst;
    }
    __syncthreads();

    {
        const float fz = ssz_s[0][p] + ssz_s[1][p];
        const float ft = sst_s[0][p] + sst_s[1][p];
        invz_s[p] = 1.f / fmaxf(sqrtf(fz), 1e-6f);
        invt_s[p] = 1.f / fmaxf(sqrtf(ft), 1e-6f);
    }
    __syncthreads();

    // ---- emit: warp e -> output channels [70e, 70e+70), lane -> 4-px group ----
    const int e  = wid;
    const int g  = lane;
    const int gy = g >> 3;
    const int gx = (g & 7) * 4;
    const int p0 = gy * 32 + gx;

    const float4 iz4 = *reinterpret_cast<const float4*>(&invz_s[p0]);
    const float4 it4 = *reinterpret_cast<const float4*>(&invt_s[p0]);

    const int s = ((ty0 + gy) << 6) + tx0 + gx;
    float* op = out + (size_t)b * COUT * HW + s;
    const float* ctr = zt + gy * ROWW + gx + ROWW + 1;   // + c*CH_STRIDE

    int ch = 70 * e;
    const int chHi = ch + 70;

    for (; ch < 32 && ch < chHi; ch++) {
        const float* zz = ctr + ch * CH_STRIDE;
        float4 o;
        o.x = zz[0] * iz4.x;
        o.y = zz[1] * iz4.y;
        o.z = zz[2] * iz4.z;
        o.w = zz[3] * iz4.w;
        *reinterpret_cast<float4*>(op + (size_t)ch * HW) = o;
    }

    if (ch < chHi) {
        int k = ch - 32;
        int i = 0;
        while (32 * (i + 1) - ((i + 1) * i) / 2 <= k) i++;
        int j = i + (k - (32 * i - (i * (i - 1)) / 2));

        float4 s4;
        s4.x = iz4.x * it4.x;
        s4.y = iz4.y * it4.y;
        s4.z = iz4.z * it4.z;
        s4.w = iz4.w * it4.w;

        const float* zz = ctr + i * CH_STRIDE;
        float4 zin;
        zin.x = zz[0] * s4.x;
        zin.y = zz[1] * s4.y;
        zin.z = zz[2] * s4.z;
        zin.w = zz[3] * s4.w;

        float* pdst = op + (size_t)ch * HW;
#pragma unroll 4
        for (; ch < chHi; ch++) {
            float4 zj = *reinterpret_cast<const float4*>(&zc_s[j * 128 + p0]);
            float4 o;
            o.x = zin.x * zj.x;
            o.y = zin.y * zj.y;
            o.z = zin.z * zj.z;
            o.w = zin.w * zj.w;
            *reinterpret_cast<float4*>(pdst) = o;
            pdst += HW;
            if (++j == CR) {
                ++i;
                j = i;
                if (i < CR) {
                    const float* z2 = ctr + i * CH_STRIDE;
                    zin.x = z2[0] * s4.x;
                    zin.y = z2[1] * s4.y;
                    zin.z = z2[2] * s4.z;
                    zin.w = z2[3] * s4.w;
                }
            }
        }
    }
}

extern "C" void kernel_launch(void* const* d_in, const int* in_sizes, int n_in,
                              void* d_out, int out_size)
{
    const float* x     = (const float*)d_in[0];
    const float* w     = (const float*)d_in[1];
    const float* gamma = (const float*)d_in[2];
    const float* beta  = (const float*)d_in[3];
    const float* mean  = (const float*)d_in[4];
    const float* var   = (const float*)d_in[5];
    const float* dw    = (const float*)d_in[6];
    const float* scale = (const float*)d_in[7];

    k_reduce<<<512, 512>>>(x, w, gamma, beta, mean, var);
    k_head<<<dim3(64 / TW, 64 / TH, B_), 256>>>(dw, scale, (float*)d_out);
}

// round 11
// speedup vs baseline: 1.3931x; 1.3931x over previous
#include <cuda_runtime.h>
#include <cstdint>

#define B_   16
#define CIN  256
#define CR   32
#define HW   4096          // 64*64
#define COUT 560           // 32 + 528

// 16 MB scratch: two K-half partial sums of the 1x1 conv (BN-scale folded,
// bias/ReLU deferred to k_head)
__device__ float g_zp[2][B_ * CR * HW];

__device__ __forceinline__ unsigned long long pack2(float lo, float hi) {
    unsigned long long r;
    asm("mov.b64 %0, {%1, %2};" : "=l"(r) : "r"(__float_as_uint(lo)), "r"(__float_as_uint(hi)));
    return r;
}
__device__ __forceinline__ unsigned long long fma2(unsigned long long a,
                                                   unsigned long long b,
                                                   unsigned long long c) {
    unsigned long long d;
    asm("fma.rn.f32x2 %0, %1, %2, %3;" : "=l"(d) : "l"(a), "l"(b), "l"(c));
    return d;
}
__device__ __forceinline__ void unpack2(unsigned long long v, float& lo, float& hi) {
    unsigned int l, h;
    asm("mov.b64 {%0, %1}, %2;" : "=r"(l), "=r"(h) : "l"(v));
    lo = __uint_as_float(l);
    hi = __uint_as_float(h);
}

// ---------------------------------------------------------------------------
// Kernel 1 (R4 verbatim — measured 41.7us): 1x1 reduce conv, K-split 2.
// 256 threads = 2 channel-halves x 128 pixel-pair slots; each thread:
// 16 output channels x 2 adjacent pixels (LDG.64), 16 f32x2 accumulators.
// ---------------------------------------------------------------------------
__global__ __launch_bounds__(256, 4) void k_reduce(
    const float* __restrict__ x, const float* __restrict__ w,
    const float* __restrict__ gamma, const float* __restrict__ var)
{
    __shared__ __align__(16) float wsm[128 * CR];  // [c_local][o], BN inv folded
    __shared__ float inv_s[CR];

    const int tid = threadIdx.x;
    const int kh  = blockIdx.y;            // input channels kh*128 .. +128

    if (tid < CR)
        inv_s[tid] = gamma[tid] * rsqrtf(var[tid] + 1e-5f);
    __syncthreads();
    for (int i = tid; i < 128 * CR; i += 256) {
        int c = i >> 5, o = i & 31;        // c local
        wsm[i] = w[o * CIN + kh * 128 + c] * inv_s[o];
    }
    __syncthreads();

    const int h    = tid >> 7;             // channel half (warp-uniform)
    const int slot = tid & 127;            // pixel-pair slot
    const int base = blockIdx.x * 256;     // 256 pixels per block
    const int b    = base >> 12;           // 16 blocks per image
    const int s0   = (base & 4095) + slot * 2;

    const float* xp = x + ((size_t)(b * CIN + kh * 128) << 12) + s0;

    unsigned long long acc0[8], acc1[8];   // [q] for px0 / px1
#pragma unroll
    for (int m = 0; m < 8; m++) { acc0[m] = 0ull; acc1[m] = 0ull; }

#pragma unroll 4
    for (int c = 0; c < 128; c++) {
        float2 a = *reinterpret_cast<const float2*>(xp + (c << 12));  // LDG.64
        unsigned long long a0 = pack2(a.x, a.x);
        unsigned long long a1 = pack2(a.y, a.y);
        const ulonglong2* wr =
            reinterpret_cast<const ulonglong2*>(wsm + c * CR + h * 16);
#pragma unroll
        for (int q = 0; q < 4; q++) {
            ulonglong2 w2 = wr[q];          // 4 output channels (2 f32x2)
            acc0[2 * q]     = fma2(a0, w2.x, acc0[2 * q]);
            acc0[2 * q + 1] = fma2(a0, w2.y, acc0[2 * q + 1]);
            acc1[2 * q]     = fma2(a1, w2.x, acc1[2 * q]);
            acc1[2 * q + 1] = fma2(a1, w2.y, acc1[2 * q + 1]);
        }
    }

    float* zp = g_zp[kh] + ((size_t)(b * CR) << 12) + s0;
#pragma unroll
    for (int m = 0; m < 8; m++) {
        float p0lo, p0hi, p1lo, p1hi;
        unpack2(acc0[m], p0lo, p0hi);
        unpack2(acc1[m], p1lo, p1hi);
        const int ch = h * 16 + 2 * m;
        *reinterpret_cast<float2*>(zp + ((size_t)ch << 12))       = make_float2(p0lo, p1lo);
        *reinterpret_cast<float2*>(zp + ((size_t)(ch + 1) << 12)) = make_float2(p0hi, p1hi);
    }
}

// ---------------------------------------------------------------------------
// Kernel 2 (R7 verbatim — measured 32.1us): combine K-halves + bias + ReLU,
// depthwise 3x3 + scale, dual L2-normalize, triu pairs, concat.
// 32x4 pixel tile, 256 threads.
// ---------------------------------------------------------------------------
#define TW 32
#define TH 4
#define ROWW 34                       // TW + 2 halo
#define NPX  204                      // 6 * 34 halo'd pixels per channel
#define CH_STRIDE NPX

__global__ __launch_bounds__(256, 4) void k_head(
    const float* __restrict__ gamma, const float* __restrict__ beta,
    const float* __restrict__ mean,  const float* __restrict__ var,
    const float* __restrict__ dw,    const float* __restrict__ scale,
    float* __restrict__ out)
{
    __shared__ float zt[CR * CH_STRIDE];     // relu'd z tile with halo (25.5KB)
    __shared__ __align__(16) float zc_s[CR * 128];  // conv*scale per pixel (16KB)
    __shared__ float ssz_s[2][128];
    __shared__ float sst_s[2][128];
    __shared__ __align__(16) float invz_s[128];
    __shared__ __align__(16) float invt_s[128];
    __shared__ float dws[CR * 9];
    __shared__ float sc_s[CR];
    __shared__ float bias_s[CR];

    const int tid  = threadIdx.x;
    const int lane = tid & 31;
    const int wid  = tid >> 5;
    const int b    = blockIdx.z;
    const int ty0  = blockIdx.y * TH;
    const int tx0  = blockIdx.x * TW;
    const int half = tid >> 7;               // 0 or 1
    const int p    = tid & 127;              // pixel within tile
    const int pty  = p >> 5;
    const int ptx  = p & 31;

    if (tid < CR) {
        float inv = gamma[tid] * rsqrtf(var[tid] + 1e-5f);
        bias_s[tid] = beta[tid] - mean[tid] * inv;
        sc_s[tid]   = scale[tid];
    }
    for (int i = tid; i < CR * 9; i += 256) dws[i] = dw[i];
    __syncthreads();   // bias_s ready before tile load

    // ---- tile load: warp `wid` handles channels wid, wid+8, wid+16, wid+24 ----
    int  offs[7];
    bool vld[7];
#pragma unroll
    for (int it = 0; it < 7; it++) {
        int px = it * 32 + lane;             // 0..223, valid < NPX
        int y  = px / ROWW;
        int xx = px - y * ROWW;
        int gy = ty0 - 1 + y;
        int gx = tx0 - 1 + xx;
        vld[it]  = (px < NPX) && ((unsigned)gy < 64u) && ((unsigned)gx < 64u);
        offs[it] = (gy << 6) + gx;
    }
    const float* z0 = g_zp[0] + (((size_t)(b * CR)) << 12);
    const float* z1 = g_zp[1] + (((size_t)(b * CR)) << 12);
#pragma unroll
    for (int cc = 0; cc < 4; cc++) {
        const int c = cc * 8 + wid;
        const float* zc0 = z0 + ((size_t)c << 12);
        const float* zc1 = z1 + ((size_t)c << 12);
        const float bc = bias_s[c];
        float* st = zt + c * CH_STRIDE;
#pragma unroll
        for (int it = 0; it < 7; it++) {
            float v = 0.f;
            if (vld[it])
                v = fmaxf(__ldg(zc0 + offs[it]) + __ldg(zc1 + offs[it]) + bc, 0.f);
            int px = it * 32 + lane;
            if (px < NPX) st[px] = v;
        }
    }
    __syncthreads();

    // ---- conv: each thread does 16 channels for its pixel ----
    {
        float ssz = 0.f, sst = 0.f;
        const int cBase = half * 16;
#pragma unroll
        for (int cc = 0; cc < 16; cc++) {
            const int c = cBase + cc;
            const float* pp = zt + c * CH_STRIDE + pty * ROWW + ptx;
            const float* k9 = dws + c * 9;
            float acc;
            acc = pp[0] * k9[0];
            acc = fmaf(pp[1],            k9[1], acc);
            acc = fmaf(pp[2],            k9[2], acc);
            acc = fmaf(pp[ROWW],         k9[3], acc);
            float ctr = pp[ROWW + 1];
            acc = fmaf(ctr,              k9[4], acc);
            acc = fmaf(pp[ROWW + 2],     k9[5], acc);
            acc = fmaf(pp[2 * ROWW],     k9[6], acc);
            acc = fmaf(pp[2 * ROWW + 1], k9[7], acc);
            acc = fmaf(pp[2 * ROWW + 2], k9[8], acc);
            acc *= sc_s[c];
            zc_s[c * 128 + p] = acc;
            ssz = fmaf(ctr, ctr, ssz);
            sst = fmaf(acc, acc, sst);
        }
        ssz_s[half][p] = ssz;
        sst_s[half][p] = sst;
    }
    __syncthreads();

    {
        const float fz = ssz_s[0][p] + ssz_s[1][p];
        const float ft = sst_s[0][p] + sst_s[1][p];
        invz_s[p] = 1.f / fmaxf(sqrtf(fz), 1e-6f);
        invt_s[p] = 1.f / fmaxf(sqrtf(ft), 1e-6f);
    }
    __syncthreads();

    // ---- emit: warp e -> output channels [70e, 70e+70), lane -> 4-px group ----
    const int e  = wid;
    const int g  = lane;
    const int gy = g >> 3;
    const int gx = (g & 7) * 4;
    const int p0 = gy * 32 + gx;

    const float4 iz4 = *reinterpret_cast<const float4*>(&invz_s[p0]);
    const float4 it4 = *reinterpret_cast<const float4*>(&invt_s[p0]);

    const int s = ((ty0 + gy) << 6) + tx0 + gx;
    float* op = out + (size_t)b * COUT * HW + s;
    const float* ctr = zt + gy * ROWW + gx + ROWW + 1;   // + c*CH_STRIDE

    int ch = 70 * e;
    const int chHi = ch + 70;

    for (; ch < 32 && ch < chHi; ch++) {
        const float* zz = ctr + ch * CH_STRIDE;
        float4 o;
        o.x = zz[0] * iz4.x;
        o.y = zz[1] * iz4.y;
        o.z = zz[2] * iz4.z;
        o.w = zz[3] * iz4.w;
        *reinterpret_cast<float4*>(op + (size_t)ch * HW) = o;
    }

    if (ch < chHi) {
        int k = ch - 32;
        int i = 0;
        while (32 * (i + 1) - ((i + 1) * i) / 2 <= k) i++;
        int j = i + (k - (32 * i - (i * (i - 1)) / 2));

        float4 s4;
        s4.x = iz4.x * it4.x;
        s4.y = iz4.y * it4.y;
        s4.z = iz4.z * it4.z;
        s4.w = iz4.w * it4.w;

        const float* zz = ctr + i * CH_STRIDE;
        float4 zin;
        zin.x = zz[0] * s4.x;
        zin.y = zz[1] * s4.y;
        zin.z = zz[2] * s4.z;
        zin.w = zz[3] * s4.w;

        float* pdst = op + (size_t)ch * HW;
#pragma unroll 4
        for (; ch < chHi; ch++) {
            float4 zj = *reinterpret_cast<const float4*>(&zc_s[j * 128 + p0]);
            float4 o;
            o.x = zin.x * zj.x;
            o.y = zin.y * zj.y;
            o.z = zin.z * zj.z;
            o.w = zin.w * zj.w;
            *reinterpret_cast<float4*>(pdst) = o;
            pdst += HW;
            if (++j == CR) {
                ++i;
                j = i;
                if (i < CR) {
                    const float* z2 = ctr + i * CH_STRIDE;
                    zin.x = z2[0] * s4.x;
                    zin.y = z2[1] * s4.y;
                    zin.z = z2[2] * s4.z;
                    zin.w = z2[3] * s4.w;
                }
            }
        }
    }
}

extern "C" void kernel_launch(void* const* d_in, const int* in_sizes, int n_in,
                              void* d_out, int out_size)
{
    const float* x     = (const float*)d_in[0];
    const float* w     = (const float*)d_in[1];
    const float* gamma = (const float*)d_in[2];
    const float* beta  = (const float*)d_in[3];
    const float* mean  = (const float*)d_in[4];
    const float* var   = (const float*)d_in[5];
    const float* dw    = (const float*)d_in[6];
    const float* scale = (const float*)d_in[7];

    k_reduce<<<dim3(256, 2), 256>>>(x, w, gamma, var);
    k_head<<<dim3(64 / TW, 64 / TH, B_), 256>>>(gamma, beta, mean, var,
                                                dw, scale, (float*)d_out);
}